// round 1
// baseline (speedup 1.0000x reference)
#include <cuda_runtime.h>
#include <math_constants.h>

#define MDATA 250000
#define NPH 4
#define NK 6
#define NMC 64
#define KN (NK*NMC)
#define NROWS (NPH+NK)
#define TPB 256
#define NBLK 245   // ceil((MDATA/4)/TPB) = ceil(62500/256)

__device__ float g_partials[NBLK];

__global__ void __launch_bounds__(TPB) bimm_main_kernel(
    const float* __restrict__ gu, const float* __restrict__ gv,
    const float* __restrict__ geps, const float* __restrict__ gI,
    const float* __restrict__ gW, const float* __restrict__ gsb,
    const float* __restrict__ gsn, const float* __restrict__ gd,
    const float* __restrict__ gr)
{
    __shared__ float sCin[KN];
    __shared__ float sT1[KN];
    __shared__ float sT2[KN];
    __shared__ float sLw[NROWS];
    __shared__ float sCI[NPH];
    __shared__ float sDI[NPH];
    __shared__ float sRed[TPB/32];

    const int tid = threadIdx.x;
    const float E = 1.44269504088896340736f;   // log2(e)

    // scalars (cheap, every thread)
    const float sb  = gsb[0];
    const float sn  = gsn[0];
    const float dd  = gd[0];
    const float rho = tanhf(gr[0]);
    const float omr = 1.0f - rho;
    const float s2  = sn * sn * omr;           // sigma_n^2 (1-rho)
    const float sr  = sn * sqrtf(omr);
    const float isn = 1.0f / sn;
    const float isn2 = isn * isn;
    const float k_u = -0.5f * E * isn2;        // per-m exponent const (u part)
    const float k_v = -E / s2;                 // per-m exponent const (v part)

    // ---- per-block table setup (384 entries, redundant per block — negligible) ----
    {
        const int IAc[NK] = {0,0,0,1,1,2};
        const int IBc[NK] = {1,2,3,2,3,3};
        const float invs2 = 1.0f / s2;
        for (int kn = tid; kn < KN; kn += TPB) {
            int k = kn >> 6;
            float Ia = gI[IAc[k]];
            float Ib = gI[IBc[k]];
            float dI = Ib - Ia;
            float x  = geps[kn] * (2.0f*dd*sb) - dd*sb;
            float z  = x / (1.41421356237309515f * sb);
            float In = (erff(z) + 1.0f) * 0.5f * dI + Ia;
            // erfinv(erf(z)) == z  =>  G = dI/sqrt(2 pi sb^2) * exp(-z^2)
            float G  = dI * rsqrtf(2.0f * CUDART_PI_F * sb * sb) * expf(-z*z);
            sCin[kn] = E * isn2 * In;                                   // coeff of u
            sT1[kn]  = -0.5f*E*isn2*In*In - E*G*G*invs2 - log2f(G);     // n-only const
            sT2[kn]  = E * 2.0f * G * invs2;                            // coeff of +-v
        }
        if (tid < NPH) {
            float Ip = gI[tid];
            sCI[tid] = E * isn2 * Ip;
            sDI[tid] = -0.5f * E * isn2 * Ip * Ip;
        }
        if (tid == 0) {
            float mw = gW[0];
            for (int j = 1; j < NROWS; j++) mw = fmaxf(mw, gW[j]);
            float sw = 0.0f;
            for (int j = 0; j < NROWS; j++) sw += expf(gW[j] - mw);
            float lse = mw + logf(sw);
            for (int j = 0; j < NROWS; j++) sLw[j] = E * (gW[j] - lse); // log2 log_softmax
        }
    }
    __syncthreads();

    // row constants (log2 units)
    // interior: E*(ln2 - ln(Gamma(1.5)) - 3 ln sr - ln sn - 0.5 ln(2 pi))
    const float cI2 = E * (0.69314718056f + 0.12078223764f
                           - 3.0f*logf(sr) - logf(sn) - 0.5f*1.83787706641f);
    // interface: E*( -ln(sn*sr*pi*sqrt(2)) - ln(NMC) )
    const float cC2 = E * (-logf(sn*sr*CUDART_PI_F*1.41421356237f) - logf((float)NMC));

    float acc = 0.0f;
    const int t = blockIdx.x * TPB + tid;
    if (t * 4 < MDATA) {
        float4 u4 = reinterpret_cast<const float4*>(gu)[t];
        float4 v4 = reinterpret_cast<const float4*>(gv)[t];
        float uA[4] = {u4.x, u4.y, u4.z, u4.w};
        float vA[4] = {v4.x, v4.y, v4.z, v4.w};
        float l2v[4], pmv[4];
        #pragma unroll
        for (int i = 0; i < 4; i++) {
            l2v[i] = log2f(vA[i]);
            pmv[i] = k_u * uA[i] * uA[i] + k_v * vA[i] * vA[i];
        }

        float rif[NK][4];
        #pragma unroll 1
        for (int k = 0; k < NK; k++) {
            const float* __restrict__ pC  = sCin + (k << 6);
            const float* __restrict__ pT1 = sT1  + (k << 6);
            const float* __restrict__ pT2 = sT2  + (k << 6);
            float S1[4] = {0.f,0.f,0.f,0.f};
            float S2[4] = {0.f,0.f,0.f,0.f};
            #pragma unroll 8
            for (int n = 0; n < NMC; n++) {
                float cin = pC[n];
                float t1  = pT1[n];
                float t2  = pT2[n];
                #pragma unroll
                for (int i = 0; i < 4; i++) {
                    float e1 = fmaf(uA[i],  cin, t1);
                    float ep = fmaf(vA[i],  t2,  e1);
                    float em = fmaf(-vA[i], t2,  e1);
                    S1[i] += exp2f(ep);
                    S2[i] += exp2f(em);
                }
            }
            #pragma unroll
            for (int i = 0; i < 4; i++) {
                float dS = fmaxf(S1[i] - S2[i], 1e-37f);  // mathematically > 0
                rif[k][i] = log2f(dS) + cC2 + l2v[i];
            }
        }

        // final 10-row logsumexp per m (log2 domain), per-m const pmv added once
        #pragma unroll
        for (int i = 0; i < 4; i++) {
            float rows[NROWS];
            float mx = -CUDART_INF_F;
            #pragma unroll
            for (int p = 0; p < NPH; p++) {
                float rr = cI2 + 2.0f*l2v[i] + fmaf(uA[i], sCI[p], sDI[p]) + sLw[p];
                rows[p] = rr;
                mx = fmaxf(mx, rr);
            }
            #pragma unroll
            for (int k = 0; k < NK; k++) {
                float rr = rif[k][i] + sLw[NPH + k];
                rows[NPH + k] = rr;
                mx = fmaxf(mx, rr);
            }
            float s = 0.0f;
            #pragma unroll
            for (int j = 0; j < NROWS; j++) s += exp2f(rows[j] - mx);
            acc += pmv[i] + mx + log2f(s);
        }
    }

    // deterministic block reduction
    #pragma unroll
    for (int o = 16; o > 0; o >>= 1) acc += __shfl_down_sync(0xffffffffu, acc, o);
    if ((tid & 31) == 0) sRed[tid >> 5] = acc;
    __syncthreads();
    if (tid == 0) {
        float s = 0.0f;
        for (int w = 0; w < TPB/32; w++) s += sRed[w];
        g_partials[blockIdx.x] = s;
    }
}

__global__ void bimm_reduce_kernel(float* out) {
    __shared__ float sRed[8];
    int tid = threadIdx.x;
    float a = (tid < NBLK) ? g_partials[tid] : 0.0f;
    #pragma unroll
    for (int o = 16; o > 0; o >>= 1) a += __shfl_down_sync(0xffffffffu, a, o);
    if ((tid & 31) == 0) sRed[tid >> 5] = a;
    __syncthreads();
    if (tid == 0) {
        float s = 0.0f;
        #pragma unroll
        for (int w = 0; w < 8; w++) s += sRed[w];
        // convert log2-sum to nats, negate, mean
        out[0] = -s * (0.69314718055994530942f / (float)MDATA);
    }
}

extern "C" void kernel_launch(void* const* d_in, const int* in_sizes, int n_in,
                              void* d_out, int out_size) {
    (void)in_sizes; (void)n_in; (void)out_size;
    bimm_main_kernel<<<NBLK, TPB>>>(
        (const float*)d_in[0], (const float*)d_in[1], (const float*)d_in[2],
        (const float*)d_in[3], (const float*)d_in[4], (const float*)d_in[5],
        (const float*)d_in[6], (const float*)d_in[7], (const float*)d_in[8]);
    bimm_reduce_kernel<<<1, 256>>>((float*)d_out);
}

// round 2
// speedup vs baseline: 1.0006x; 1.0006x over previous
#include <cuda_runtime.h>
#include <math_constants.h>

#define MDATA 250000
#define NPH 4
#define NK 6
#define NMC 64
#define KN (NK*NMC)
#define NROWS (NPH+NK)
#define TPB 256
#define NBLK 245   // ceil((MDATA/4)/TPB) = ceil(62500/256)

__device__ float g_partials[NBLK];

__global__ void __launch_bounds__(TPB) bimm_main_kernel(
    const float* __restrict__ gu, const float* __restrict__ gv,
    const float* __restrict__ geps, const float* __restrict__ gI,
    const float* __restrict__ gW, const float* __restrict__ gsb,
    const float* __restrict__ gsn, const float* __restrict__ gd,
    const float* __restrict__ gr)
{
    __shared__ float sCin[KN];
    __shared__ float sT1[KN];
    __shared__ float sT2[KN];
    __shared__ float sLw[NROWS];
    __shared__ float sCI[NPH];
    __shared__ float sDI[NPH];
    __shared__ float sRed[TPB/32];

    const int tid = threadIdx.x;
    const float E = 1.44269504088896340736f;   // log2(e)

    // scalars (cheap, every thread)
    const float sb  = gsb[0];
    const float sn  = gsn[0];
    const float dd  = gd[0];
    const float rho = tanhf(gr[0]);
    const float omr = 1.0f - rho;
    const float s2  = sn * sn * omr;           // sigma_n^2 (1-rho)
    const float sr  = sn * sqrtf(omr);
    const float isn = 1.0f / sn;
    const float isn2 = isn * isn;
    const float k_u = -0.5f * E * isn2;        // per-m exponent const (u part)
    const float k_v = -E / s2;                 // per-m exponent const (v part)

    // ---- per-block table setup (384 entries, redundant per block — negligible) ----
    {
        const int IAc[NK] = {0,0,0,1,1,2};
        const int IBc[NK] = {1,2,3,2,3,3};
        const float invs2 = 1.0f / s2;
        for (int kn = tid; kn < KN; kn += TPB) {
            int k = kn >> 6;
            float Ia = gI[IAc[k]];
            float Ib = gI[IBc[k]];
            float dI = Ib - Ia;
            float x  = geps[kn] * (2.0f*dd*sb) - dd*sb;
            float z  = x / (1.41421356237309515f * sb);
            float In = (erff(z) + 1.0f) * 0.5f * dI + Ia;
            // erfinv(erf(z)) == z  =>  G = dI/sqrt(2 pi sb^2) * exp(-z^2)
            float G  = dI * rsqrtf(2.0f * CUDART_PI_F * sb * sb) * expf(-z*z);
            sCin[kn] = E * isn2 * In;                                   // coeff of u
            sT1[kn]  = -0.5f*E*isn2*In*In - E*G*G*invs2 - log2f(G);     // n-only const
            sT2[kn]  = E * 2.0f * G * invs2;                            // coeff of +-v
        }
        if (tid < NPH) {
            float Ip = gI[tid];
            sCI[tid] = E * isn2 * Ip;
            sDI[tid] = -0.5f * E * isn2 * Ip * Ip;
        }
        if (tid == 0) {
            float mw = gW[0];
            for (int j = 1; j < NROWS; j++) mw = fmaxf(mw, gW[j]);
            float sw = 0.0f;
            for (int j = 0; j < NROWS; j++) sw += expf(gW[j] - mw);
            float lse = mw + logf(sw);
            for (int j = 0; j < NROWS; j++) sLw[j] = E * (gW[j] - lse); // log2 log_softmax
        }
    }
    __syncthreads();

    // row constants (log2 units)
    // interior: E*(ln2 - ln(Gamma(1.5)) - 3 ln sr - ln sn - 0.5 ln(2 pi))
    const float cI2 = E * (0.69314718056f + 0.12078223764f
                           - 3.0f*logf(sr) - logf(sn) - 0.5f*1.83787706641f);
    // interface: E*( -ln(sn*sr*pi*sqrt(2)) - ln(NMC) )
    const float cC2 = E * (-logf(sn*sr*CUDART_PI_F*1.41421356237f) - logf((float)NMC));

    float acc = 0.0f;
    const int t = blockIdx.x * TPB + tid;
    if (t * 4 < MDATA) {
        float4 u4 = reinterpret_cast<const float4*>(gu)[t];
        float4 v4 = reinterpret_cast<const float4*>(gv)[t];
        float uA[4] = {u4.x, u4.y, u4.z, u4.w};
        float vA[4] = {v4.x, v4.y, v4.z, v4.w};
        float l2v[4], pmv[4];
        #pragma unroll
        for (int i = 0; i < 4; i++) {
            l2v[i] = log2f(vA[i]);
            pmv[i] = k_u * uA[i] * uA[i] + k_v * vA[i] * vA[i];
        }

        float rif[NK][4];
        #pragma unroll 1
        for (int k = 0; k < NK; k++) {
            const float* __restrict__ pC  = sCin + (k << 6);
            const float* __restrict__ pT1 = sT1  + (k << 6);
            const float* __restrict__ pT2 = sT2  + (k << 6);
            float S1[4] = {0.f,0.f,0.f,0.f};
            float S2[4] = {0.f,0.f,0.f,0.f};
            #pragma unroll 8
            for (int n = 0; n < NMC; n++) {
                float cin = pC[n];
                float t1  = pT1[n];
                float t2  = pT2[n];
                #pragma unroll
                for (int i = 0; i < 4; i++) {
                    float e1 = fmaf(uA[i],  cin, t1);
                    float ep = fmaf(vA[i],  t2,  e1);
                    float em = fmaf(-vA[i], t2,  e1);
                    S1[i] += exp2f(ep);
                    S2[i] += exp2f(em);
                }
            }
            #pragma unroll
            for (int i = 0; i < 4; i++) {
                float dS = fmaxf(S1[i] - S2[i], 1e-37f);  // mathematically > 0
                rif[k][i] = log2f(dS) + cC2 + l2v[i];
            }
        }

        // final 10-row logsumexp per m (log2 domain), per-m const pmv added once
        #pragma unroll
        for (int i = 0; i < 4; i++) {
            float rows[NROWS];
            float mx = -CUDART_INF_F;
            #pragma unroll
            for (int p = 0; p < NPH; p++) {
                float rr = cI2 + 2.0f*l2v[i] + fmaf(uA[i], sCI[p], sDI[p]) + sLw[p];
                rows[p] = rr;
                mx = fmaxf(mx, rr);
            }
            #pragma unroll
            for (int k = 0; k < NK; k++) {
                float rr = rif[k][i] + sLw[NPH + k];
                rows[NPH + k] = rr;
                mx = fmaxf(mx, rr);
            }
            float s = 0.0f;
            #pragma unroll
            for (int j = 0; j < NROWS; j++) s += exp2f(rows[j] - mx);
            acc += pmv[i] + mx + log2f(s);
        }
    }

    // deterministic block reduction
    #pragma unroll
    for (int o = 16; o > 0; o >>= 1) acc += __shfl_down_sync(0xffffffffu, acc, o);
    if ((tid & 31) == 0) sRed[tid >> 5] = acc;
    __syncthreads();
    if (tid == 0) {
        float s = 0.0f;
        for (int w = 0; w < TPB/32; w++) s += sRed[w];
        g_partials[blockIdx.x] = s;
    }
}

__global__ void bimm_reduce_kernel(float* out) {
    __shared__ float sRed[8];
    int tid = threadIdx.x;
    float a = (tid < NBLK) ? g_partials[tid] : 0.0f;
    #pragma unroll
    for (int o = 16; o > 0; o >>= 1) a += __shfl_down_sync(0xffffffffu, a, o);
    if ((tid & 31) == 0) sRed[tid >> 5] = a;
    __syncthreads();
    if (tid == 0) {
        float s = 0.0f;
        #pragma unroll
        for (int w = 0; w < 8; w++) s += sRed[w];
        // convert log2-sum to nats, negate, mean
        out[0] = -s * (0.69314718055994530942f / (float)MDATA);
    }
}

extern "C" void kernel_launch(void* const* d_in, const int* in_sizes, int n_in,
                              void* d_out, int out_size) {
    (void)in_sizes; (void)n_in; (void)out_size;
    bimm_main_kernel<<<NBLK, TPB>>>(
        (const float*)d_in[0], (const float*)d_in[1], (const float*)d_in[2],
        (const float*)d_in[3], (const float*)d_in[4], (const float*)d_in[5],
        (const float*)d_in[6], (const float*)d_in[7], (const float*)d_in[8]);
    bimm_reduce_kernel<<<1, 256>>>((float*)d_out);
}

// round 3
// speedup vs baseline: 1.8829x; 1.8818x over previous
#include <cuda_runtime.h>
#include <math_constants.h>

#define MDATA 250000
#define NPH 4
#define NK 6
#define NMC 64
#define NROWS (NPH+NK)

#define NUI 48                 // u intervals
#define NVI 32                 // v intervals
#define NUN (NUI+1)            // 49 u nodes
#define NVN (NVI+1)            // 33 v nodes
#define NODES_K (NUN*NVN)      // 1617
#define TOT_NODES (NODES_K*NK) // 9702

#define V0C 0.01f
#define HUC (1.0f/48.0f)
#define HVC (0.3f/32.0f)

#define TPB 512
#define NBLK 152               // GB300: 152 SMs
#define CHUNK ((MDATA + NBLK - 1)/NBLK)

__device__ float4 g_table[TOT_NODES];
__device__ float  g_partials[NBLK];
__device__ unsigned int g_count = 0;

// ---------------------------------------------------------------------------
// Build: one warp per table node. f = log2( sum_n exp(u*B+A) * 2sinh(C v)/v )
// plus exact derivatives fu, fv, fuv (log2 units) via posterior expectations.
// ---------------------------------------------------------------------------
__global__ void bimm_build_kernel(
    const float* __restrict__ geps, const float* __restrict__ gI,
    const float* __restrict__ gsb, const float* __restrict__ gsn,
    const float* __restrict__ gd,  const float* __restrict__ gr)
{
    int wid_g = (int)((blockIdx.x * blockDim.x + threadIdx.x) >> 5);
    int lane  = threadIdx.x & 31;
    if (wid_g >= TOT_NODES) return;

    int k  = wid_g / NODES_K;
    int rm = wid_g - k * NODES_K;
    int iu = rm / NVN;
    int iv = rm - iu * NVN;
    float u = iu * HUC;
    float v = V0C + iv * HVC;

    const int IAc[NK] = {0,0,0,1,1,2};
    const int IBc[NK] = {1,2,3,2,3,3};
    float sb  = gsb[0];
    float sn  = gsn[0];
    float dd  = gd[0];
    float rho = tanhf(gr[0]);
    float s2  = sn * sn * (1.0f - rho);
    float isn2 = 1.0f / (sn * sn);
    float Ia = gI[IAc[k]];
    float Ib = gI[IBc[k]];
    float dI = Ib - Ia;
    float gc = dI * rsqrtf(2.0f * CUDART_PI_F * sb * sb);

    float S = 0.f, Sb = 0.f, Sg = 0.f, Sbg = 0.f;
    #pragma unroll
    for (int h = 0; h < 2; h++) {
        int n = lane + 32 * h;
        float ep = geps[k * NMC + n];
        float x  = ep * (2.0f * dd * sb) - dd * sb;
        float z  = x / (1.41421356237309515f * sb);
        float In = (erff(z) + 1.0f) * 0.5f * dI + Ia;
        float G  = gc * expf(-z * z);            // erfinv(erf(z)) == z
        float B  = In * isn2;                    // d/du (nats)
        float A  = -0.5f * In * In * isn2 - G * G / s2 - logf(G);
        float C  = 2.0f * G / s2;
        float xx = C * v;
        float ex  = expf(xx);
        float iex = 1.0f / ex;
        float sh2 = ex - iex;                    // 2 sinh(xx)
        float P;                                 // xx*coth(xx) - 1
        if (xx < 0.3f) {
            float x2 = xx * xx;
            P = x2 * (0.33333333333f + x2 * (-0.0222222222f + x2 * 0.0021164021f));
        } else {
            P = xx * (ex + iex) / sh2 - 1.0f;
        }
        float g = P / v;                         // d/dv (nats)
        float q = expf(fmaf(u, B, A)) * sh2 / v;
        S   += q;
        Sb  += q * B;
        Sg  += q * g;
        Sbg += q * B * g;
    }
    #pragma unroll
    for (int o = 16; o; o >>= 1) {
        S   += __shfl_xor_sync(0xffffffffu, S,   o);
        Sb  += __shfl_xor_sync(0xffffffffu, Sb,  o);
        Sg  += __shfl_xor_sync(0xffffffffu, Sg,  o);
        Sbg += __shfl_xor_sync(0xffffffffu, Sbg, o);
    }
    if (lane == 0) {
        const float IE = 1.44269504088896340736f;  // 1/ln2
        float invS = 1.0f / S;
        float fu = Sb * invS;
        float fv = Sg * invS;
        float4 o;
        o.x = log2f(S);
        o.y = fu * IE;
        o.z = fv * IE;
        o.w = (Sbg * invS - fu * fv) * IE;
        g_table[wid_g] = o;
    }
}

// ---------------------------------------------------------------------------
// Main: stage table to shared, bicubic Hermite per (m, k), 10-row LSE,
// fused deterministic final reduction (last-block ticket).
// ---------------------------------------------------------------------------
__global__ void __launch_bounds__(TPB, 1) bimm_main_kernel(
    const float* __restrict__ gu, const float* __restrict__ gv,
    const float* __restrict__ gI, const float* __restrict__ gW,
    const float* __restrict__ gsn, const float* __restrict__ gr,
    float* __restrict__ out)
{
    extern __shared__ float4 stab[];
    __shared__ float sRed[TPB / 32];
    __shared__ bool s_last;

    const int tid = threadIdx.x;
    const float E = 1.44269504088896340736f;

    for (int i = tid; i < TOT_NODES; i += TPB) stab[i] = g_table[i];

    const float sn  = gsn[0];
    const float rho = tanhf(gr[0]);
    const float omr = 1.0f - rho;
    const float s2  = sn * sn * omr;
    const float sr  = sn * sqrtf(omr);
    const float isn2 = 1.0f / (sn * sn);
    const float k_u = -0.5f * E * isn2;
    const float k_v = -E / s2;

    // interior row const (log2): ln2 - lnGamma(1.5) - 3 ln sr - ln sn - 0.5 ln 2pi
    const float cI2 = E * (0.69314718056f + 0.12078223764f
                           - 3.0f * logf(sr) - logf(sn) - 0.5f * 1.83787706641f);
    // interface row const (log2): -ln(sn*sr*pi*sqrt2) - ln N_MC
    const float cC2 = E * (-logf(sn * sr * CUDART_PI_F * 1.41421356237f)
                           - logf((float)NMC));

    float lw[NROWS];
    {
        float wv[NROWS];
        float mw = -CUDART_INF_F;
        #pragma unroll
        for (int j = 0; j < NROWS; j++) { wv[j] = gW[j]; mw = fmaxf(mw, wv[j]); }
        float sw = 0.0f;
        #pragma unroll
        for (int j = 0; j < NROWS; j++) sw += expf(wv[j] - mw);
        float lse = mw + logf(sw);
        #pragma unroll
        for (int j = 0; j < NROWS; j++) lw[j] = E * (wv[j] - lse);
    }
    float cIp[NPH], dIp[NPH];
    #pragma unroll
    for (int p = 0; p < NPH; p++) {
        float Ip = gI[p];
        cIp[p] = E * isn2 * Ip;
        dIp[p] = -0.5f * E * isn2 * Ip * Ip;
    }
    __syncthreads();

    float acc = 0.0f;
    const int m0   = blockIdx.x * CHUNK;
    const int mend = min(m0 + CHUNK, MDATA);

    for (int m = m0 + tid; m < mend; m += TPB) {
        float u = gu[m];
        float v = gv[m];
        float l2v = log2f(v);
        float pm = k_u * u * u + k_v * v * v + 2.0f * l2v;

        float su = u * (float)NUI;
        int iu = (int)su; iu = min(max(iu, 0), NUI - 1);
        float s = su - (float)iu;
        float sv = (v - V0C) * ((float)NVI / 0.3f);
        int iv = (int)sv; iv = min(max(iv, 0), NVI - 1);
        float t = sv - (float)iv;

        float ss = s * s, s3 = ss * s;
        float Au0 = 2.0f * s3 - 3.0f * ss + 1.0f;
        float Au1 = (s3 - 2.0f * ss + s) * HUC;
        float Au2 = 3.0f * ss - 2.0f * s3;
        float Au3 = (s3 - ss) * HUC;
        float tt = t * t, t3 = tt * t;
        float Av0 = 2.0f * t3 - 3.0f * tt + 1.0f;
        float Av1 = (t3 - 2.0f * tt + t) * HVC;
        float Av2 = 3.0f * tt - 2.0f * t3;
        float Av3 = (t3 - tt) * HVC;

        float W00 = Au0*Av0, W01 = Au0*Av1, W02 = Au0*Av2, W03 = Au0*Av3;
        float W10 = Au1*Av0, W11 = Au1*Av1, W12 = Au1*Av2, W13 = Au1*Av3;
        float W20 = Au2*Av0, W21 = Au2*Av1, W22 = Au2*Av2, W23 = Au2*Av3;
        float W30 = Au3*Av0, W31 = Au3*Av1, W32 = Au3*Av2, W33 = Au3*Av3;

        int base = iu * NVN + iv;

        float rows[NROWS];
        float mx = -CUDART_INF_F;
        #pragma unroll
        for (int p = 0; p < NPH; p++) {
            float rr = cI2 + fmaf(u, cIp[p], dIp[p]) + lw[p];
            rows[p] = rr; mx = fmaxf(mx, rr);
        }
        #pragma unroll
        for (int k = 0; k < NK; k++) {
            const float4* tb = stab + (k * NODES_K + base);
            float4 c00 = tb[0];
            float4 c01 = tb[1];
            float4 c10 = tb[NVN];
            float4 c11 = tb[NVN + 1];
            float f;
            f  = W00 * c00.x + W10 * c00.y + W01 * c00.z + W11 * c00.w;
            f += W20 * c10.x + W30 * c10.y + W21 * c10.z + W31 * c10.w;
            f += W02 * c01.x + W12 * c01.y + W03 * c01.z + W13 * c01.w;
            f += W22 * c11.x + W32 * c11.y + W23 * c11.z + W33 * c11.w;
            float rr = f + cC2 + lw[NPH + k];
            rows[NPH + k] = rr; mx = fmaxf(mx, rr);
        }
        float sum = 0.0f;
        #pragma unroll
        for (int j = 0; j < NROWS; j++) sum += exp2f(rows[j] - mx);
        acc += pm + mx + log2f(sum);
    }

    // deterministic block reduction
    #pragma unroll
    for (int o = 16; o > 0; o >>= 1) acc += __shfl_down_sync(0xffffffffu, acc, o);
    if ((tid & 31) == 0) sRed[tid >> 5] = acc;
    __syncthreads();
    if (tid == 0) {
        float bs = 0.0f;
        #pragma unroll
        for (int w = 0; w < TPB / 32; w++) bs += sRed[w];
        g_partials[blockIdx.x] = bs;
        __threadfence();
        unsigned int ticket = atomicAdd(&g_count, 1u);
        s_last = (ticket == NBLK - 1);
    }
    __syncthreads();

    if (s_last) {
        // last block: deterministic final sum over fixed-order partials
        float a = 0.0f;
        if (tid < 32) {
            for (int i = tid; i < NBLK; i += 32) a += g_partials[i];
            #pragma unroll
            for (int o = 16; o > 0; o >>= 1) a += __shfl_down_sync(0xffffffffu, a, o);
            if (tid == 0) {
                out[0] = -a * (0.69314718055994530942f / (float)MDATA);
                g_count = 0;   // reset for next graph replay
            }
        }
    }
}

extern "C" void kernel_launch(void* const* d_in, const int* in_sizes, int n_in,
                              void* d_out, int out_size) {
    (void)in_sizes; (void)n_in; (void)out_size;
    const float* gu   = (const float*)d_in[0];
    const float* gv   = (const float*)d_in[1];
    const float* geps = (const float*)d_in[2];
    const float* gI   = (const float*)d_in[3];
    const float* gW   = (const float*)d_in[4];
    const float* gsb  = (const float*)d_in[5];
    const float* gsn  = (const float*)d_in[6];
    const float* gd   = (const float*)d_in[7];
    const float* gr   = (const float*)d_in[8];

    static bool attr_done = false;
    if (!attr_done) {
        cudaFuncSetAttribute(bimm_main_kernel,
                             cudaFuncAttributeMaxDynamicSharedMemorySize,
                             TOT_NODES * (int)sizeof(float4));
        attr_done = true;
    }

    int build_blocks = (TOT_NODES * 32 + 255) / 256;
    bimm_build_kernel<<<build_blocks, 256>>>(geps, gI, gsb, gsn, gd, gr);
    bimm_main_kernel<<<NBLK, TPB, TOT_NODES * sizeof(float4)>>>(
        gu, gv, gI, gW, gsn, gr, (float*)d_out);
}

// round 4
// speedup vs baseline: 2.1326x; 1.1326x over previous
#include <cuda_runtime.h>
#include <math_constants.h>

#define MDATA 250000
#define NPH 4
#define NK 6
#define NMC 64
#define NROWS (NPH+NK)

#define NUI 48                 // u intervals
#define NVI 32                 // v intervals
#define NUN (NUI+1)            // 49 u nodes
#define NVN (NVI+1)            // 33 v nodes (odd stride: conflict-friendly)
#define NODES_K (NUN*NVN)      // 1617
#define TOT_NODES (NODES_K*NK) // 9702

#define V0C 0.01f
#define HUC (1.0f/48.0f)
#define HVC (0.3f/32.0f)

#define TPB 1024
#define NBLK 152               // GB300: 152 SMs
#define CHUNK ((MDATA + NBLK - 1)/NBLK)

__device__ float4 g_table[TOT_NODES];
__device__ float  g_partials[NBLK];
__device__ unsigned int g_count = 0;

// ---------------------------------------------------------------------------
// Build: one warp per node. f = log2( sum_n exp(u*B+A) * 2sinh(C v)/v ) and
// exact derivatives fu, fv, fuv (log2 units) via posterior expectations.
// ---------------------------------------------------------------------------
__global__ void bimm_build_kernel(
    const float* __restrict__ geps, const float* __restrict__ gI,
    const float* __restrict__ gsb, const float* __restrict__ gsn,
    const float* __restrict__ gd,  const float* __restrict__ gr)
{
    int wid_g = (int)((blockIdx.x * blockDim.x + threadIdx.x) >> 5);
    int lane  = threadIdx.x & 31;
    if (wid_g >= TOT_NODES) return;

    int k  = wid_g / NODES_K;
    int rm = wid_g - k * NODES_K;
    int iu = rm / NVN;
    int iv = rm - iu * NVN;
    float u = iu * HUC;
    float v = V0C + iv * HVC;

    const int IAc[NK] = {0,0,0,1,1,2};
    const int IBc[NK] = {1,2,3,2,3,3};
    float sb  = gsb[0];
    float sn  = gsn[0];
    float dd  = gd[0];
    float rho = tanhf(gr[0]);
    float s2  = sn * sn * (1.0f - rho);
    float isn2 = 1.0f / (sn * sn);
    float Ia = gI[IAc[k]];
    float Ib = gI[IBc[k]];
    float dI = Ib - Ia;
    float gc = dI * rsqrtf(2.0f * CUDART_PI_F * sb * sb);

    float S = 0.f, Sb = 0.f, Sg = 0.f, Sbg = 0.f;
    #pragma unroll
    for (int h = 0; h < 2; h++) {
        int n = lane + 32 * h;
        float ep = geps[k * NMC + n];
        float x  = ep * (2.0f * dd * sb) - dd * sb;
        float z  = x / (1.41421356237309515f * sb);
        float In = (erff(z) + 1.0f) * 0.5f * dI + Ia;
        float G  = gc * expf(-z * z);            // erfinv(erf(z)) == z
        float B  = In * isn2;                    // d/du (nats)
        float A  = -0.5f * In * In * isn2 - G * G / s2 - logf(G);
        float C  = 2.0f * G / s2;
        float xx = C * v;
        float ex  = expf(xx);
        float iex = 1.0f / ex;
        float sh2 = ex - iex;                    // 2 sinh(xx)
        float P;                                 // xx*coth(xx) - 1
        if (xx < 0.3f) {
            float x2 = xx * xx;
            P = x2 * (0.33333333333f + x2 * (-0.0222222222f + x2 * 0.0021164021f));
        } else {
            P = xx * (ex + iex) / sh2 - 1.0f;
        }
        float g = P / v;                         // d/dv (nats)
        float q = expf(fmaf(u, B, A)) * sh2 / v;
        S   += q;
        Sb  += q * B;
        Sg  += q * g;
        Sbg += q * B * g;
    }
    #pragma unroll
    for (int o = 16; o; o >>= 1) {
        S   += __shfl_xor_sync(0xffffffffu, S,   o);
        Sb  += __shfl_xor_sync(0xffffffffu, Sb,  o);
        Sg  += __shfl_xor_sync(0xffffffffu, Sg,  o);
        Sbg += __shfl_xor_sync(0xffffffffu, Sbg, o);
    }
    if (lane == 0) {
        const float IE = 1.44269504088896340736f;
        float invS = 1.0f / S;
        float fu = Sb * invS;
        float fv = Sg * invS;
        float4 o;
        o.x = log2f(S);
        o.y = fu * IE;
        o.z = fv * IE;
        o.w = (Sbg * invS - fu * fv) * IE;
        g_table[wid_g] = o;
    }
}

// ---------------------------------------------------------------------------
// Main: stage table to shared; per m: bicubic Hermite x6 + 4 interior rows,
// direct exp2 sum (no max needed; bounded ~2^95), fused final reduction.
// ---------------------------------------------------------------------------
__global__ void __launch_bounds__(TPB, 1) bimm_main_kernel(
    const float* __restrict__ gu, const float* __restrict__ gv,
    const float* __restrict__ gI, const float* __restrict__ gW,
    const float* __restrict__ gsn, const float* __restrict__ gr,
    float* __restrict__ out)
{
    extern __shared__ float4 stab[];
    __shared__ float sRed[TPB / 32];
    __shared__ float sA[NPH];     // interior: coef of u (log2)
    __shared__ float sB[NPH];     // interior: const incl. lw (log2)
    __shared__ float sE[NK];      // interface: const incl. lw (log2)
    __shared__ bool  s_last;

    const int tid = threadIdx.x;
    const float E = 1.44269504088896340736f;

    for (int i = tid; i < TOT_NODES; i += TPB) stab[i] = g_table[i];

    const float sn  = gsn[0];
    const float rho = tanhf(gr[0]);
    const float omr = 1.0f - rho;
    const float s2  = sn * sn * omr;
    const float sr  = sn * sqrtf(omr);
    const float isn2 = 1.0f / (sn * sn);
    const float k_u = -0.5f * E * isn2;
    const float k_v = -E / s2;

    if (tid == 0) {
        // log-softmax of W
        float wv[NROWS];
        float mw = -CUDART_INF_F;
        #pragma unroll
        for (int j = 0; j < NROWS; j++) { wv[j] = gW[j]; mw = fmaxf(mw, wv[j]); }
        float sw = 0.0f;
        #pragma unroll
        for (int j = 0; j < NROWS; j++) sw += expf(wv[j] - mw);
        float lse = mw + logf(sw);

        float cI2 = E * (0.69314718056f + 0.12078223764f
                         - 3.0f * logf(sr) - logf(sn) - 0.5f * 1.83787706641f);
        float cC2 = E * (-logf(sn * sr * CUDART_PI_F * 1.41421356237f)
                         - logf((float)NMC));
        #pragma unroll
        for (int p = 0; p < NPH; p++) {
            float Ip = gI[p];
            sA[p] = E * isn2 * Ip;
            sB[p] = cI2 - 0.5f * E * isn2 * Ip * Ip + E * (wv[p] - lse);
        }
        #pragma unroll
        for (int k = 0; k < NK; k++)
            sE[k] = cC2 + E * (wv[NPH + k] - lse);
    }
    __syncthreads();

    float acc = 0.0f;
    const int m0   = blockIdx.x * CHUNK;
    const int mend = min(m0 + CHUNK, MDATA);

    for (int m = m0 + tid; m < mend; m += TPB) {
        float u = gu[m];
        float v = gv[m];
        float l2v = log2f(v);
        float pm = k_u * u * u + k_v * v * v + 2.0f * l2v;

        float su = u * (float)NUI;
        int iu = (int)su; iu = min(max(iu, 0), NUI - 1);
        float s = su - (float)iu;
        float sv = (v - V0C) * ((float)NVI / 0.3f);
        int iv = (int)sv; iv = min(max(iv, 0), NVI - 1);
        float t = sv - (float)iv;

        float ss = s * s, s3 = ss * s;
        float Au0 = 2.0f * s3 - 3.0f * ss + 1.0f;
        float Au1 = (s3 - 2.0f * ss + s) * HUC;
        float Au2 = 3.0f * ss - 2.0f * s3;
        float Au3 = (s3 - ss) * HUC;
        float tt = t * t, t3 = tt * t;
        float Av0 = 2.0f * t3 - 3.0f * tt + 1.0f;
        float Av1 = (t3 - 2.0f * tt + t) * HVC;
        float Av2 = 3.0f * tt - 2.0f * t3;
        float Av3 = (t3 - tt) * HVC;

        int base = iu * NVN + iv;

        float sum = 0.0f;
        #pragma unroll
        for (int p = 0; p < NPH; p++)
            sum += exp2f(fmaf(u, sA[p], sB[p]));
        #pragma unroll
        for (int k = 0; k < NK; k++) {
            const float4* tb = stab + (k * NODES_K + base);
            float4 c00 = tb[0];
            float4 c01 = tb[1];
            float4 c10 = tb[NVN];
            float4 c11 = tb[NVN + 1];
            // nested dot products: f = sum_i Au_i * (sum_j Av_j * c_ij)
            float P0 = Av0*c00.x + Av1*c00.z + Av2*c01.x + Av3*c01.z;
            float P1 = Av0*c00.y + Av1*c00.w + Av2*c01.y + Av3*c01.w;
            float P2 = Av0*c10.x + Av1*c10.z + Av2*c11.x + Av3*c11.z;
            float P3 = Av0*c10.y + Av1*c10.w + Av2*c11.y + Av3*c11.w;
            float f  = Au0*P0 + Au1*P1 + Au2*P2 + Au3*P3;
            sum += exp2f(f + sE[k]);
        }
        acc += pm + log2f(sum);
    }

    // deterministic block reduction
    #pragma unroll
    for (int o = 16; o > 0; o >>= 1) acc += __shfl_down_sync(0xffffffffu, acc, o);
    if ((tid & 31) == 0) sRed[tid >> 5] = acc;
    __syncthreads();
    if (tid == 0) {
        float bs = 0.0f;
        #pragma unroll
        for (int w = 0; w < TPB / 32; w++) bs += sRed[w];
        g_partials[blockIdx.x] = bs;
        __threadfence();
        unsigned int ticket = atomicAdd(&g_count, 1u);
        s_last = (ticket == NBLK - 1);
    }
    __syncthreads();

    if (s_last) {
        float a = 0.0f;
        if (tid < 32) {
            for (int i = tid; i < NBLK; i += 32) a += g_partials[i];
            #pragma unroll
            for (int o = 16; o > 0; o >>= 1) a += __shfl_down_sync(0xffffffffu, a, o);
            if (tid == 0) {
                out[0] = -a * (0.69314718055994530942f / (float)MDATA);
                g_count = 0;   // reset for next graph replay
            }
        }
    }
}

extern "C" void kernel_launch(void* const* d_in, const int* in_sizes, int n_in,
                              void* d_out, int out_size) {
    (void)in_sizes; (void)n_in; (void)out_size;
    const float* gu   = (const float*)d_in[0];
    const float* gv   = (const float*)d_in[1];
    const float* geps = (const float*)d_in[2];
    const float* gI   = (const float*)d_in[3];
    const float* gW   = (const float*)d_in[4];
    const float* gsb  = (const float*)d_in[5];
    const float* gsn  = (const float*)d_in[6];
    const float* gd   = (const float*)d_in[7];
    const float* gr   = (const float*)d_in[8];

    static bool attr_done = false;
    if (!attr_done) {
        cudaFuncSetAttribute(bimm_main_kernel,
                             cudaFuncAttributeMaxDynamicSharedMemorySize,
                             TOT_NODES * (int)sizeof(float4));
        attr_done = true;
    }

    int build_blocks = (TOT_NODES * 32 + 255) / 256;
    bimm_build_kernel<<<build_blocks, 256>>>(geps, gI, gsb, gsn, gd, gr);
    bimm_main_kernel<<<NBLK, TPB, TOT_NODES * sizeof(float4)>>>(
        gu, gv, gI, gW, gsn, gr, (float*)d_out);
}

// round 5
// speedup vs baseline: 2.8150x; 1.3200x over previous
#include <cuda_runtime.h>
#include <math_constants.h>

#define MDATA 250000
#define NPH 4
#define NK 6
#define NMC 64
#define KN (NK*NMC)
#define NROWS (NPH+NK)

#define NUI 192
#define NVI 32
#define NUN (NUI+1)            // 193
#define NVN (NVI+1)            // 33
#define NODES (NUN*NVN)        // 6369  -> 99.5 KB table

#define V0C 0.01f
#define HUC (1.0f/192.0f)
#define HVC (0.3f/32.0f)

#define TPB 1024
#define NBLK 152
#define CHUNK ((MDATA + NBLK - 1)/NBLK)

__device__ float4 g_table[NODES];
__device__ float4 g_kn[KN];        // (B*IE, A'*IE, C*IE, B)  per (k,n)
__device__ float2 g_int[NPH];      // (alpha, beta) nats, weights folded
__device__ float  g_partials[NBLK];
__device__ unsigned int g_count = 0;

// ---------------------------------------------------------------------------
// Precompute per-(k,n) and per-interior constants (weights + all row consts
// folded). One small block.
// ---------------------------------------------------------------------------
__global__ void bimm_pre_kernel(
    const float* __restrict__ geps, const float* __restrict__ gI,
    const float* __restrict__ gW,  const float* __restrict__ gsb,
    const float* __restrict__ gsn, const float* __restrict__ gd,
    const float* __restrict__ gr)
{
    const int tid = threadIdx.x;
    const float IE = 1.44269504088896340736f;

    float sb  = gsb[0];
    float sn  = gsn[0];
    float dd  = gd[0];
    float rho = tanhf(gr[0]);
    float omr = 1.0f - rho;
    float s2  = sn * sn * omr;
    float sr  = sn * sqrtf(omr);
    float isn2 = 1.0f / (sn * sn);

    // log-softmax of W (nats)
    float wv[NROWS];
    float mw = -CUDART_INF_F;
    #pragma unroll
    for (int j = 0; j < NROWS; j++) { wv[j] = gW[j]; mw = fmaxf(mw, wv[j]); }
    float sw = 0.0f;
    #pragma unroll
    for (int j = 0; j < NROWS; j++) sw += expf(wv[j] - mw);
    float lse = mw + logf(sw);

    // row constants (nats)
    float cIn = 0.69314718056f + 0.12078223764f
                - 3.0f * logf(sr) - logf(sn) - 0.5f * 1.83787706641f;
    float cCn = -logf(sn * sr * CUDART_PI_F * 1.41421356237f)
                - logf((float)NMC);

    if (tid < KN) {
        const int IAc[NK] = {0,0,0,1,1,2};
        const int IBc[NK] = {1,2,3,2,3,3};
        int k = tid >> 6;
        float Ia = gI[IAc[k]];
        float Ib = gI[IBc[k]];
        float dI = Ib - Ia;
        float gc = dI * rsqrtf(2.0f * CUDART_PI_F * sb * sb);
        float x  = geps[tid] * (2.0f * dd * sb) - dd * sb;
        float z  = x / (1.41421356237309515f * sb);
        float In = (erff(z) + 1.0f) * 0.5f * dI + Ia;
        float G  = gc * expf(-z * z);          // erfinv(erf(z)) == z
        float B  = In * isn2;
        float Ap = -0.5f * In * In * isn2 - G * G / s2 - logf(G)
                   + cCn + (wv[NPH + k] - lse);
        float C  = 2.0f * G / s2;
        g_kn[tid] = make_float4(B * IE, Ap * IE, C * IE, B);
    }
    if (tid < NPH) {
        float Ip = gI[tid];
        g_int[tid] = make_float2(Ip * isn2,
                                 -0.5f * Ip * Ip * isn2 + cIn + (wv[tid] - lse));
    }
}

// ---------------------------------------------------------------------------
// Build: one warp per node. H = log2( sum_interior + sum_{k,n} terms ) with
// exact derivatives Hu, Hv, Huv via linear-space accumulation.
// ---------------------------------------------------------------------------
__global__ void __launch_bounds__(256) bimm_build_kernel()
{
    int gw   = (int)((blockIdx.x * blockDim.x + threadIdx.x) >> 5);
    int lane = threadIdx.x & 31;
    if (gw >= NODES) return;

    int iu = gw / NVN;
    int iv = gw - iu * NVN;
    float u = iu * HUC;
    float v = V0C + iv * HVC;
    float inv_v = 1.0f / v;
    const float LN2 = 0.69314718055994530942f;
    const float IE  = 1.44269504088896340736f;

    float sT = 0.f, sTu = 0.f, sTv = 0.f, sTuv = 0.f;
    #pragma unroll
    for (int t = 0; t < KN / 32; t++) {
        float4 c = g_kn[lane + (t << 5)];
        float e1 = fmaf(u, c.x, c.y);
        float qh = exp2f(e1);                  // exp(uB + A')
        float xn = c.z * v;                    // C*v in log2 units
        float ex  = exp2f(xn);
        float iex = exp2f(-xn);
        float sh = ex - iex;                   // 2 sinh(Cv)
        float ch = ex + iex;                   // 2 cosh(Cv)
        float Cn = c.z * LN2;                  // C (nats)
        float tv = fmaf(Cn, ch, -sh * inv_v);  // d/dv of 2sinh(Cv)/v, * v
        float qs = qh * sh;
        float qt = qh * tv;
        sT   += qs;
        sTv  += qt;
        sTu  = fmaf(qs, c.w, sTu);
        sTuv = fmaf(qt, c.w, sTuv);
    }
    #pragma unroll
    for (int o = 16; o; o >>= 1) {
        sT   += __shfl_xor_sync(0xffffffffu, sT,   o);
        sTu  += __shfl_xor_sync(0xffffffffu, sTu,  o);
        sTv  += __shfl_xor_sync(0xffffffffu, sTv,  o);
        sTuv += __shfl_xor_sync(0xffffffffu, sTuv, o);
    }
    if (lane == 0) {
        float T   = sT   * inv_v;
        float Tu  = sTu  * inv_v;
        float Tv  = sTv  * inv_v;
        float Tuv = sTuv * inv_v;
        #pragma unroll
        for (int p = 0; p < NPH; p++) {
            float2 ab = g_int[p];
            float tp = expf(fmaf(u, ab.x, ab.y));
            T  += tp;
            Tu = fmaf(ab.x, tp, Tu);
        }
        float invT = 1.0f / T;
        float hu = Tu * invT;
        float hv = Tv * invT;
        float4 o;
        o.x = log2f(T);
        o.y = hu * IE;
        o.z = hv * IE;
        o.w = (Tuv * invT - hu * hv) * IE;
        g_table[gw] = o;
    }
}

// ---------------------------------------------------------------------------
// Main: stage 99.5KB table to shared; per point: ONE bicubic Hermite + pm.
// Fused deterministic final reduction (last-block ticket).
// ---------------------------------------------------------------------------
__global__ void __launch_bounds__(TPB, 1) bimm_main_kernel(
    const float* __restrict__ gu, const float* __restrict__ gv,
    const float* __restrict__ gsn, const float* __restrict__ gr,
    float* __restrict__ out)
{
    extern __shared__ float4 stab[];
    __shared__ float sRed[TPB / 32];
    __shared__ bool  s_last;

    const int tid = threadIdx.x;
    const float E = 1.44269504088896340736f;

    for (int i = tid; i < NODES; i += TPB) stab[i] = g_table[i];

    const float sn  = gsn[0];
    const float rho = tanhf(gr[0]);
    const float s2  = sn * sn * (1.0f - rho);
    const float k_u = -0.5f * E / (sn * sn);
    const float k_v = -E / s2;
    __syncthreads();

    float acc = 0.0f;
    const int m0   = blockIdx.x * CHUNK;
    const int mend = min(m0 + CHUNK, MDATA);

    for (int m = m0 + tid; m < mend; m += TPB) {
        float u = gu[m];
        float v = gv[m];
        float l2v = log2f(v);
        float pm = k_u * u * u + k_v * v * v + 2.0f * l2v;

        float su = u * (float)NUI;
        int iu = (int)su; iu = min(max(iu, 0), NUI - 1);
        float s = su - (float)iu;
        float sv = (v - V0C) * ((float)NVI / 0.3f);
        int iv = (int)sv; iv = min(max(iv, 0), NVI - 1);
        float t = sv - (float)iv;

        float ss = s * s, s3 = ss * s;
        float Au0 = 2.0f * s3 - 3.0f * ss + 1.0f;
        float Au1 = (s3 - 2.0f * ss + s) * HUC;
        float Au2 = 3.0f * ss - 2.0f * s3;
        float Au3 = (s3 - ss) * HUC;
        float tt = t * t, t3 = tt * t;
        float Av0 = 2.0f * t3 - 3.0f * tt + 1.0f;
        float Av1 = (t3 - 2.0f * tt + t) * HVC;
        float Av2 = 3.0f * tt - 2.0f * t3;
        float Av3 = (t3 - tt) * HVC;

        const float4* tb = stab + (iu * NVN + iv);
        float4 c00 = tb[0];
        float4 c01 = tb[1];
        float4 c10 = tb[NVN];
        float4 c11 = tb[NVN + 1];
        float P0 = Av0*c00.x + Av1*c00.z + Av2*c01.x + Av3*c01.z;
        float P1 = Av0*c00.y + Av1*c00.w + Av2*c01.y + Av3*c01.w;
        float P2 = Av0*c10.x + Av1*c10.z + Av2*c11.x + Av3*c11.z;
        float P3 = Av0*c10.y + Av1*c10.w + Av2*c11.y + Av3*c11.w;
        float f  = Au0*P0 + Au1*P1 + Au2*P2 + Au3*P3;

        acc += pm + f;
    }

    // deterministic block reduction
    #pragma unroll
    for (int o = 16; o > 0; o >>= 1) acc += __shfl_down_sync(0xffffffffu, acc, o);
    if ((tid & 31) == 0) sRed[tid >> 5] = acc;
    __syncthreads();
    if (tid == 0) {
        float bs = 0.0f;
        #pragma unroll
        for (int w = 0; w < TPB / 32; w++) bs += sRed[w];
        g_partials[blockIdx.x] = bs;
        __threadfence();
        unsigned int ticket = atomicAdd(&g_count, 1u);
        s_last = (ticket == NBLK - 1);
    }
    __syncthreads();

    if (s_last) {
        float a = 0.0f;
        if (tid < 32) {
            for (int i = tid; i < NBLK; i += 32) a += g_partials[i];
            #pragma unroll
            for (int o = 16; o > 0; o >>= 1) a += __shfl_down_sync(0xffffffffu, a, o);
            if (tid == 0) {
                out[0] = -a * (0.69314718055994530942f / (float)MDATA);
                g_count = 0;   // reset for next graph replay
            }
        }
    }
}

extern "C" void kernel_launch(void* const* d_in, const int* in_sizes, int n_in,
                              void* d_out, int out_size) {
    (void)in_sizes; (void)n_in; (void)out_size;
    const float* gu   = (const float*)d_in[0];
    const float* gv   = (const float*)d_in[1];
    const float* geps = (const float*)d_in[2];
    const float* gI   = (const float*)d_in[3];
    const float* gW   = (const float*)d_in[4];
    const float* gsb  = (const float*)d_in[5];
    const float* gsn  = (const float*)d_in[6];
    const float* gd   = (const float*)d_in[7];
    const float* gr   = (const float*)d_in[8];

    static bool attr_done = false;
    if (!attr_done) {
        cudaFuncSetAttribute(bimm_main_kernel,
                             cudaFuncAttributeMaxDynamicSharedMemorySize,
                             NODES * (int)sizeof(float4));
        attr_done = true;
    }

    bimm_pre_kernel<<<1, 512>>>(geps, gI, gW, gsb, gsn, gd, gr);
    int build_blocks = (NODES * 32 + 255) / 256;
    bimm_build_kernel<<<build_blocks, 256>>>();
    bimm_main_kernel<<<NBLK, TPB, NODES * sizeof(float4)>>>(
        gu, gv, gsn, gr, (float*)d_out);
}